// round 7
// baseline (speedup 1.0000x reference)
#include <cuda_runtime.h>
#include <math.h>

// Problem constants (fixed shapes)
#define NB 8
#define NT 256
#define ND 512
#define NS 256
#define NV 32000
#define NL 2
#define NM (NB*NT)   // 2048 rows

// ---------------------------------------------------------------------------
// Scratch (static device globals — no allocation)
// ---------------------------------------------------------------------------
__device__ float g_xenc [NM*ND];   // x @ enc_W + enc_b, precomputed for all t
__device__ float g_preds[NM*ND];   // final_pred per (b,t)
__device__ float g_h    [NM*ND];   // gelu(LN(preds))
__device__ int   g_rowflag[NM/64]; // per-64-row block: any nonzero in h?

// ---------------------------------------------------------------------------
// Block-wide (sum, sumsq) reduction for 512 threads (16 warps) — epilogue only
// ---------------------------------------------------------------------------
__device__ __forceinline__ float2 blk_sum2(float v, float v2, float2* red)
{
    #pragma unroll
    for (int o = 16; o > 0; o >>= 1) {
        v  += __shfl_xor_sync(0xffffffffu, v,  o);
        v2 += __shfl_xor_sync(0xffffffffu, v2, o);
    }
    const int w = threadIdx.x >> 5;
    const int lane = threadIdx.x & 31;
    if (lane == 0) red[w] = make_float2(v, v2);
    __syncthreads();
    if (w == 0) {
        float a = (lane < 16) ? red[lane].x : 0.f;
        float b = (lane < 16) ? red[lane].y : 0.f;
        #pragma unroll
        for (int o = 8; o > 0; o >>= 1) {
            a += __shfl_xor_sync(0xffffffffu, a, o);
            b += __shfl_xor_sync(0xffffffffu, b, o);
        }
        if (lane == 0) red[16] = make_float2(a, b);
    }
    __syncthreads();
    return red[16];
}

// ---------------------------------------------------------------------------
// Init: zero row flags
// ---------------------------------------------------------------------------
__global__ void init_k()
{
    if (threadIdx.x < NM/64) g_rowflag[threadIdx.x] = 0;
}

// ---------------------------------------------------------------------------
// Encoder GEMM with fused embedding gather:
//   g_xenc[m,n] = sum_k (tok[ids[m],k] + pos[m%T,k]) * W[k,n] + b[n]
// M=2048, N=512, K=512.  BM=64, BN=128, BK=16, 256 threads, 4x8 microtile.
// ---------------------------------------------------------------------------
__global__ __launch_bounds__(256) void enc_gemm_k(
    const int* __restrict__ ids, const float* __restrict__ tok,
    const float* __restrict__ pos, const float* __restrict__ W,
    const float* __restrict__ bias)
{
    __shared__ float As[16][65];
    __shared__ float Bs[16][128];
    __shared__ int ids_sm[64];

    const int tid = threadIdx.x;
    const int m0 = blockIdx.y * 64;
    const int n0 = blockIdx.x * 128;
    if (tid < 64) ids_sm[tid] = ids[m0 + tid];
    __syncthreads();

    const int ty = tid >> 4, tx = tid & 15;      // 16x16 thread grid
    const int arow = tid >> 2, kc = (tid & 3) * 4;
    const int gid  = ids_sm[arow];
    const int trow = (m0 + arow) & (NT - 1);     // t = m % T

    float acc[4][8];
    #pragma unroll
    for (int i = 0; i < 4; i++)
        #pragma unroll
        for (int jj = 0; jj < 8; jj++) acc[i][jj] = 0.f;

    for (int k0 = 0; k0 < ND; k0 += 16) {
        float4 t4 = *(const float4*)&tok[gid*ND + k0 + kc];
        float4 p4 = *(const float4*)&pos[trow*ND + k0 + kc];
        As[kc+0][arow] = t4.x + p4.x;
        As[kc+1][arow] = t4.y + p4.y;
        As[kc+2][arow] = t4.z + p4.z;
        As[kc+3][arow] = t4.w + p4.w;
        #pragma unroll
        for (int i = 0; i < 2; i++) {
            int idx = tid*2 + i;
            int br = idx >> 5, bc = (idx & 31) * 4;
            *(float4*)&Bs[br][bc] = *(const float4*)&W[(k0+br)*ND + n0 + bc];
        }
        __syncthreads();
        #pragma unroll
        for (int kk = 0; kk < 16; kk++) {
            float a[4], bb[8];
            #pragma unroll
            for (int i = 0; i < 4; i++) a[i] = As[kk][ty*4+i];
            #pragma unroll
            for (int jj = 0; jj < 8; jj++) bb[jj] = Bs[kk][tx*8+jj];
            #pragma unroll
            for (int i = 0; i < 4; i++)
                #pragma unroll
                for (int jj = 0; jj < 8; jj++) acc[i][jj] += a[i]*bb[jj];
        }
        __syncthreads();
    }
    #pragma unroll
    for (int i = 0; i < 4; i++) {
        const int m = m0 + ty*4 + i;
        #pragma unroll
        for (int jj = 0; jj < 8; jj++) {
            const int n = n0 + tx*8 + jj;
            g_xenc[m*ND + n] = acc[i][jj] + bias[n];
        }
    }
}

// ---------------------------------------------------------------------------
// Single-barrier block reduction for 128 threads (4 warps), double-buffered
// by parity p. Returns (sum, sumsq, any-nonzero).
// ---------------------------------------------------------------------------
struct Red3 { float s, q; int nz; };

__device__ __forceinline__ Red3 blk_reduce4(
    float s, float q, int nz, int p,
    float2 (*red2)[4], int (*rnz)[4], int w, int lane)
{
    #pragma unroll
    for (int o = 16; o > 0; o >>= 1) {
        s += __shfl_xor_sync(0xffffffffu, s, o);
        q += __shfl_xor_sync(0xffffffffu, q, o);
    }
    int wn = __any_sync(0xffffffffu, nz);
    if (lane == 0) { red2[p][w] = make_float2(s, q); rnz[p][w] = wn; }
    __syncthreads();
    Red3 r; r.s = 0.f; r.q = 0.f; r.nz = 0;
    #pragma unroll
    for (int i = 0; i < 4; i++) {
        float2 v = red2[p][i];
        r.s += v.x; r.q += v.y; r.nz |= rnz[p][i];
    }
    return r;
}

// ---------------------------------------------------------------------------
// Recurrence: 1 CTA per batch, 128 threads (4 D-lanes each; threads < 64 own
// 4 S-lanes). Whole 256-step scan in one kernel. Membranes in registers,
// states/err in smem. GEMVs are skipped exactly when their input vector is
// all-zero AND the LN bias feeding it is zero (then result == bias,
// bit-identical). Nonzero-vector votes are folded into the LN reductions,
// and post-write visibility barriers are conditional on those flags:
// fast path = 5 barriers/step total.
// ---------------------------------------------------------------------------
__global__ __launch_bounds__(128) void recur_k(
    const float* __restrict__ gen_W, const float* __restrict__ gen_b,
    const float* __restrict__ gen_tau, const float* __restrict__ gen_thr,
    const float* __restrict__ inf_W, const float* __restrict__ inf_b,
    const float* __restrict__ inf_tau, const float* __restrict__ inf_thr,
    const float* __restrict__ ne_g, const float* __restrict__ ne_b,
    const float* __restrict__ ns_g, const float* __restrict__ ns_b,
    const float* __restrict__ enc_tau, const float* __restrict__ enc_thr)
{
    __shared__ __align__(16) float st_sm[NL][NS];
    __shared__ __align__(16) float err_sm[ND];
    __shared__ float2 red2[2][4];
    __shared__ int    rnz[2][4];

    const int b    = blockIdx.x;
    const int tid  = threadIdx.x;
    const int w    = tid >> 5, lane = tid & 31;
    const int d0   = tid * 4;                 // owns D lanes d0..d0+3
    const bool hasS = (tid < NS/4);           // threads 0..63 own S lanes
    const int s0   = tid * 4;

    // ---- per-thread parameters (registers; init cost is negligible) ----
    float dec_e[4], thr_e[4];
    #pragma unroll
    for (int c = 0; c < 4; c++) {
        dec_e[c] = expf(-1.f / fmaxf(enc_tau[d0+c], 1.f));
        thr_e[c] = enc_thr[d0+c];
    }
    float gb[NL][4], gdec[NL][4], gthr[NL][4], negv[NL][4], nebv[NL][4];
    #pragma unroll
    for (int j = 0; j < NL; j++)
        #pragma unroll
        for (int c = 0; c < 4; c++) {
            const int i = j*ND + d0 + c;
            gb[j][c]   = gen_b[i];
            gdec[j][c] = expf(-1.f / fmaxf(gen_tau[i], 1.f));
            gthr[j][c] = gen_thr[i];
            negv[j][c] = ne_g[i];
            nebv[j][c] = ne_b[i];
        }
    float ib[NL][4], idec[NL][4], ithr[NL][4], nsgv[NL][4], nsbv[NL][4];
    #pragma unroll
    for (int j = 0; j < NL; j++)
        #pragma unroll
        for (int c = 0; c < 4; c++) {
            ib[j][c] = 0.f; idec[j][c] = 0.f; ithr[j][c] = 0.f;
            nsgv[j][c] = 0.f; nsbv[j][c] = 0.f;
        }
    if (hasS) {
        #pragma unroll
        for (int j = 0; j < NL; j++)
            #pragma unroll
            for (int c = 0; c < 4; c++) {
                const int i = j*NS + s0 + c;
                ib[j][c]   = inf_b[i];
                idec[j][c] = expf(-1.f / fmaxf(inf_tau[i], 1.f));
                ithr[j][c] = inf_thr[i];
                nsgv[j][c] = ns_g[i];
                nsbv[j][c] = ns_b[i];
            }
        #pragma unroll
        for (int c = 0; c < 4; c++) { st_sm[0][s0+c] = 0.f; st_sm[1][s0+c] = 0.f; }
    }

    // Bias-nonzero flags: if LN input is all-zero its output equals the bias,
    // so the downstream GEMV is skippable iff value_nz==0 AND bias_nz==0.
    int neb_nz[NL], nsb_nz[NL];
    #pragma unroll
    for (int j = 0; j < NL; j++) {
        int a = 0, bn = 0;
        #pragma unroll
        for (int c = 0; c < 4; c++) a |= (nebv[j][c] != 0.f);
        if (hasS)
            #pragma unroll
            for (int c = 0; c < 4; c++) bn |= (nsbv[j][c] != 0.f);
        neb_nz[j] = __syncthreads_or(a);
        nsb_nz[j] = __syncthreads_or(bn);
    }

    float m_enc[4] = {0,0,0,0};
    float m_gen[NL][4] = {{0,0,0,0},{0,0,0,0}};
    float m_inf[NL][4] = {{0,0,0,0},{0,0,0,0}};
    float st_r [NL][4] = {{0,0,0,0},{0,0,0,0}};
    int   st_nz[NL] = {0, 0};
    __syncthreads();

    const float* xp = g_xenc  + (b*NT)*ND + d0;
    float*       pp = g_preds + (b*NT)*ND + d0;
    int p = 0;  // reduction-buffer parity

    for (int t = 0; t < NT; t++) {
        // ---- input encoder LIF ----
        float bu[4];
        {
            float4 x4 = *(const float4*)&xp[t*ND];
            float xi[4] = {x4.x, x4.y, x4.z, x4.w};
            #pragma unroll
            for (int c = 0; c < 4; c++) {
                float m = m_enc[c]*dec_e[c] + xi[c];
                float s = (m >= thr_e[c]) ? 1.f : 0.f;
                m_enc[c] = m*(1.f - s);
                bu[c] = s;
            }
        }

        // ---- predictive-coding layers ----
        #pragma unroll
        for (int j = 0; j < NL; j++) {
            // generative GEMV: states[j] @ gen_W[j] + gen_b[j]
            float gin[4] = {gb[j][0], gb[j][1], gb[j][2], gb[j][3]};
            if (st_nz[j]) {
                const float* Wp = gen_W + j*(NS*ND) + d0;
                for (int k = 0; k < NS; k++) {
                    float sv = st_sm[j][k];
                    float4 w4 = *(const float4*)&Wp[k*ND];
                    gin[0] += sv*w4.x; gin[1] += sv*w4.y;
                    gin[2] += sv*w4.z; gin[3] += sv*w4.w;
                }
            }
            float v[4];
            #pragma unroll
            for (int c = 0; c < 4; c++) {
                float mg = m_gen[j][c]*gdec[j][c] + gin[c];
                float pr = (mg >= gthr[j][c]) ? 1.f : 0.f;
                m_gen[j][c] = mg*(1.f - pr);
                v[c] = bu[c] - pr;
            }
            // err = LN(bu - pred) over D
            float s = (v[0]+v[1])+(v[2]+v[3]);
            float q = (v[0]*v[0]+v[1]*v[1])+(v[2]*v[2]+v[3]*v[3]);
            int   a = (v[0]!=0.f)|(v[1]!=0.f)|(v[2]!=0.f)|(v[3]!=0.f);
            Red3 r = blk_reduce4(s, q, a, p, red2, rnz, w, lane); p ^= 1;
            float mu   = r.s * (1.f/ND);
            float rstd = rsqrtf(fmaxf(r.q*(1.f/ND) - mu*mu, 0.f) + 1e-5f);
            float e[4];
            #pragma unroll
            for (int c = 0; c < 4; c++) e[c] = (v[c]-mu)*rstd*negv[j][c] + nebv[j][c];
            *(float4*)&err_sm[d0] = make_float4(e[0], e[1], e[2], e[3]);
            const int enz = r.nz | neb_nz[j];          // uniform
            if (enz) __syncthreads();                  // err_sm visible for GEMV
            #pragma unroll
            for (int c = 0; c < 4; c++) bu[c] = e[c];

            // inference GEMV: err @ inf_W[j] + inf_b[j] (S lanes)
            float nsv[4] = {0,0,0,0};
            if (hasS) {
                float iin[4] = {ib[j][0], ib[j][1], ib[j][2], ib[j][3]};
                if (enz) {
                    const float* Wp = inf_W + j*(ND*NS) + s0;
                    for (int k = 0; k < ND; k++) {
                        float ev = err_sm[k];
                        float4 w4 = *(const float4*)&Wp[k*NS];
                        iin[0] += ev*w4.x; iin[1] += ev*w4.y;
                        iin[2] += ev*w4.z; iin[3] += ev*w4.w;
                    }
                }
                #pragma unroll
                for (int c = 0; c < 4; c++) {
                    float mi = m_inf[j][c]*idec[j][c] + iin[c];
                    float su = (mi >= ithr[j][c]) ? 1.f : 0.f;
                    m_inf[j][c] = mi*(1.f - su);
                    nsv[c] = st_r[j][c] + su;
                }
            }
            // states[j] = LN(states[j] + su) over S
            float s2 = (nsv[0]+nsv[1])+(nsv[2]+nsv[3]);
            float q2 = (nsv[0]*nsv[0]+nsv[1]*nsv[1])+(nsv[2]*nsv[2]+nsv[3]*nsv[3]);
            int   a2 = (nsv[0]!=0.f)|(nsv[1]!=0.f)|(nsv[2]!=0.f)|(nsv[3]!=0.f);
            Red3 r2 = blk_reduce4(s2, q2, a2, p, red2, rnz, w, lane); p ^= 1;
            float mu2   = r2.s * (1.f/NS);
            float rstd2 = rsqrtf(fmaxf(r2.q*(1.f/NS) - mu2*mu2, 0.f) + 1e-5f);
            if (hasS) {
                float nst[4];
                #pragma unroll
                for (int c = 0; c < 4; c++) {
                    nst[c] = (nsv[c]-mu2)*rstd2*nsgv[j][c] + nsbv[j][c];
                    st_r[j][c] = nst[c];
                }
                *(float4*)&st_sm[j][s0] = make_float4(nst[0], nst[1], nst[2], nst[3]);
            }
            const int newnz = r2.nz | nsb_nz[j];       // uniform (conservative, exact)
            if (newnz) __syncthreads();                // st_sm visible for next GEMV
            st_nz[j] = newnz;
        }

        // ---- extra decode on last layer (also advances membranes) ----
        {
            const int j = NL-1;
            float gin[4] = {gb[j][0], gb[j][1], gb[j][2], gb[j][3]};
            if (st_nz[j]) {
                const float* Wp = gen_W + j*(NS*ND) + d0;
                for (int k = 0; k < NS; k++) {
                    float sv = st_sm[j][k];
                    float4 w4 = *(const float4*)&Wp[k*ND];
                    gin[0] += sv*w4.x; gin[1] += sv*w4.y;
                    gin[2] += sv*w4.z; gin[3] += sv*w4.w;
                }
            }
            float fp[4], v[4];
            #pragma unroll
            for (int c = 0; c < 4; c++) {
                float mg = m_gen[j][c]*gdec[j][c] + gin[c];
                fp[c] = (mg >= gthr[j][c]) ? 1.f : 0.f;
                m_gen[j][c] = mg*(1.f - fp[c]);
                v[c] = -fp[c];
            }
            *(float4*)&pp[t*ND] = make_float4(fp[0], fp[1], fp[2], fp[3]);

            float s = (v[0]+v[1])+(v[2]+v[3]);
            float q = (v[0]*v[0]+v[1]*v[1])+(v[2]*v[2]+v[3]*v[3]);
            int   a = (v[0]!=0.f)|(v[1]!=0.f)|(v[2]!=0.f)|(v[3]!=0.f);
            Red3 r = blk_reduce4(s, q, a, p, red2, rnz, w, lane); p ^= 1;
            float mu   = r.s * (1.f/ND);
            float rstd = rsqrtf(fmaxf(r.q*(1.f/ND) - mu*mu, 0.f) + 1e-5f);
            float e2[4];
            #pragma unroll
            for (int c = 0; c < 4; c++) e2[c] = (v[c]-mu)*rstd*negv[j][c] + nebv[j][c];
            *(float4*)&err_sm[d0] = make_float4(e2[0], e2[1], e2[2], e2[3]);
            const int enz2 = r.nz | neb_nz[j];
            if (enz2) __syncthreads();
            if (hasS) {
                float iin[4] = {ib[j][0], ib[j][1], ib[j][2], ib[j][3]};
                if (enz2) {
                    const float* Wp = inf_W + j*(ND*NS) + s0;
                    for (int k = 0; k < ND; k++) {
                        float ev = err_sm[k];
                        float4 w4 = *(const float4*)&Wp[k*NS];
                        iin[0] += ev*w4.x; iin[1] += ev*w4.y;
                        iin[2] += ev*w4.z; iin[3] += ev*w4.w;
                    }
                }
                #pragma unroll
                for (int c = 0; c < 4; c++) {
                    float mi = m_inf[j][c]*idec[j][c] + iin[c];
                    float su = (mi >= ithr[j][c]) ? 1.f : 0.f;
                    m_inf[j][c] = mi*(1.f - su);   // membrane advances, spike dropped
                }
            }
        }
    }
}

// ---------------------------------------------------------------------------
// Epilogue: h = gelu(LN(preds)) per row; record per-64-row nonzero flags.
// ---------------------------------------------------------------------------
__global__ __launch_bounds__(512) void epilogue_k(
    const float* __restrict__ og, const float* __restrict__ ob)
{
    __shared__ float2 red[17];
    const int m = blockIdx.x;
    const int d = threadIdx.x;
    float v = g_preds[m*ND + d];
    float2 s = blk_sum2(v, v*v, red);
    float mu = s.x * (1.f/ND);
    float rstd = rsqrtf(fmaxf(s.y*(1.f/ND) - mu*mu, 0.f) + 1e-5f);
    float x = (v - mu)*rstd*og[d] + ob[d];
    float hv = 0.5f * x * (1.f + erff(x * 0.70710678118654752440f));
    g_h[m*ND + d] = hv;
    int nz = __syncthreads_or(hv != 0.f);
    if (d == 0 && nz) atomicOr(&g_rowflag[m >> 6], 1);
}

// ---------------------------------------------------------------------------
// Output GEMM: out[m,n] = h[m,:] @ out_W[:,n] + out_b2[n].
// Fast path when the 64-row block of h is all zero: broadcast the bias row
// (exact: 0 @ W + b == b). Full tiled fp32 GEMM otherwise.
// ---------------------------------------------------------------------------
__global__ __launch_bounds__(256) void out_gemm_k(
    const float* __restrict__ Wo, const float* __restrict__ bias,
    float* __restrict__ out)
{
    const int tid = threadIdx.x;
    const int m0 = blockIdx.y * 64;
    const int n0 = blockIdx.x * 128;

    if (g_rowflag[blockIdx.y] == 0) {
        const int c4 = (tid & 31) * 4;
        const int r0 = tid >> 5;
        const float4 bv = *(const float4*)&bias[n0 + c4];
        #pragma unroll
        for (int r = r0; r < 64; r += 8)
            *(float4*)&out[(m0 + r)*NV + n0 + c4] = bv;
        return;
    }

    __shared__ float As[16][65];
    __shared__ float Bs[16][128];
    const int ty = tid >> 4, tx = tid & 15;
    const int arow = tid >> 2, kc = (tid & 3) * 4;

    float acc[4][8];
    #pragma unroll
    for (int i = 0; i < 4; i++)
        #pragma unroll
        for (int jj = 0; jj < 8; jj++) acc[i][jj] = 0.f;

    for (int k0 = 0; k0 < ND; k0 += 16) {
        float4 a4 = *(const float4*)&g_h[(m0 + arow)*ND + k0 + kc];
        As[kc+0][arow] = a4.x;
        As[kc+1][arow] = a4.y;
        As[kc+2][arow] = a4.z;
        As[kc+3][arow] = a4.w;
        #pragma unroll
        for (int i = 0; i < 2; i++) {
            int idx = tid*2 + i;
            int br = idx >> 5, bc = (idx & 31) * 4;
            *(float4*)&Bs[br][bc] = *(const float4*)&Wo[(k0+br)*NV + n0 + bc];
        }
        __syncthreads();
        #pragma unroll
        for (int kk = 0; kk < 16; kk++) {
            float a[4], bb[8];
            #pragma unroll
            for (int i = 0; i < 4; i++) a[i] = As[kk][ty*4+i];
            #pragma unroll
            for (int jj = 0; jj < 8; jj++) bb[jj] = Bs[kk][tx*8+jj];
            #pragma unroll
            for (int i = 0; i < 4; i++)
                #pragma unroll
                for (int jj = 0; jj < 8; jj++) acc[i][jj] += a[i]*bb[jj];
        }
        __syncthreads();
    }
    #pragma unroll
    for (int i = 0; i < 4; i++) {
        const int m = m0 + ty*4 + i;
        #pragma unroll
        for (int jj = 0; jj < 8; jj++) {
            const int n = n0 + tx*8 + jj;
            out[m*NV + n] = acc[i][jj] + bias[n];
        }
    }
}

// ---------------------------------------------------------------------------
// Entry point
// ---------------------------------------------------------------------------
extern "C" void kernel_launch(void* const* d_in, const int* in_sizes, int n_in,
                              void* d_out, int out_size)
{
    (void)in_sizes; (void)n_in; (void)out_size;
    const int*   ids    = (const int*)  d_in[0];
    const float* tok    = (const float*)d_in[1];
    const float* pos    = (const float*)d_in[2];
    const float* encW   = (const float*)d_in[3];
    const float* encb   = (const float*)d_in[4];
    const float* enctau = (const float*)d_in[5];
    const float* encthr = (const float*)d_in[6];
    const float* genW   = (const float*)d_in[7];
    const float* genb   = (const float*)d_in[8];
    const float* gentau = (const float*)d_in[9];
    const float* genthr = (const float*)d_in[10];
    const float* infW   = (const float*)d_in[11];
    const float* infb   = (const float*)d_in[12];
    const float* inftau = (const float*)d_in[13];
    const float* infthr = (const float*)d_in[14];
    const float* neg    = (const float*)d_in[15];
    const float* neb    = (const float*)d_in[16];
    const float* nsg    = (const float*)d_in[17];
    const float* nsb    = (const float*)d_in[18];
    const float* outg   = (const float*)d_in[19];
    const float* outb   = (const float*)d_in[20];
    const float* outW   = (const float*)d_in[21];
    const float* outb2  = (const float*)d_in[22];
    float* out = (float*)d_out;

    init_k<<<1, 32>>>();
    enc_gemm_k<<<dim3(ND/128, NM/64), 256>>>(ids, tok, pos, encW, encb);
    recur_k<<<NB, 128>>>(genW, genb, gentau, genthr,
                         infW, infb, inftau, infthr,
                         neg, neb, nsg, nsb, enctau, encthr);
    epilogue_k<<<NM, ND>>>(outg, outb);
    out_gemm_k<<<dim3(NV/128, NM/64), 256>>>(outW, outb2, out);
}

// round 9
// speedup vs baseline: 2.0384x; 2.0384x over previous
#include <cuda_runtime.h>
#include <math.h>

// Problem constants (fixed shapes)
#define NB 8
#define NT 256
#define ND 512
#define NS 256
#define NV 32000
#define NL 2
#define NM (NB*NT)   // 2048 rows

// ---------------------------------------------------------------------------
// Scratch (static device globals — no allocation)
// ---------------------------------------------------------------------------
__device__ float g_xenc [NM*ND];    // x @ enc_W + enc_b, all t
__device__ float g_preds[NM*ND];    // final_pred per (b,t)
__device__ float g_h    [NM*ND];    // gelu(LN(preds))
__device__ int   g_rowflag[NM/64];  // per-64-row block: any nonzero in h?
__device__ int   g_tother;          // batch-independent first-deviation time
__device__ int   g_tbreak[NB];      // per-batch first-deviation time
__device__ float g_iin  [NL*NS];    // const inf drive: ne_b @ inf_W + inf_b
__device__ float g_menc [NB*ND];    // membrane snapshots at t_break
__device__ float g_mgen [NB*NL*ND];
__device__ float g_minf [NB*NL*NS];

// ---------------------------------------------------------------------------
// Reductions
// ---------------------------------------------------------------------------
__device__ __forceinline__ float2 blk_sum2(float v, float v2, float2* red)
{
    #pragma unroll
    for (int o = 16; o > 0; o >>= 1) {
        v  += __shfl_xor_sync(0xffffffffu, v,  o);
        v2 += __shfl_xor_sync(0xffffffffu, v2, o);
    }
    const int w = threadIdx.x >> 5;
    const int lane = threadIdx.x & 31;
    if (lane == 0) red[w] = make_float2(v, v2);
    __syncthreads();
    if (w == 0) {
        float a = (lane < 16) ? red[lane].x : 0.f;
        float b = (lane < 16) ? red[lane].y : 0.f;
        #pragma unroll
        for (int o = 8; o > 0; o >>= 1) {
            a += __shfl_xor_sync(0xffffffffu, a, o);
            b += __shfl_xor_sync(0xffffffffu, b, o);
        }
        if (lane == 0) red[16] = make_float2(a, b);
    }
    __syncthreads();
    return red[16];
}

// block-wide min over up to 512 threads (16 warps)
__device__ __forceinline__ int blk_min(int v, int* red)
{
    #pragma unroll
    for (int o = 16; o > 0; o >>= 1)
        v = min(v, __shfl_xor_sync(0xffffffffu, v, o));
    const int w = threadIdx.x >> 5;
    const int lane = threadIdx.x & 31;
    const int nw = (blockDim.x + 31) >> 5;
    if (lane == 0) red[w] = v;
    __syncthreads();
    if (w == 0) {
        int a = (lane < nw) ? red[lane] : 0x7fffffff;
        #pragma unroll
        for (int o = 8; o > 0; o >>= 1)
            a = min(a, __shfl_xor_sync(0xffffffffu, a, o));
        if (lane == 0) red[16] = a;
    }
    __syncthreads();
    return red[16];
}

// ---------------------------------------------------------------------------
// Init: zero row flags
// ---------------------------------------------------------------------------
__global__ void init_k()
{
    if (threadIdx.x < NM/64) g_rowflag[threadIdx.x] = 0;
}

// ---------------------------------------------------------------------------
// consts_k (1 CTA, 512 threads):
//  * g_iin[j,s] = inf_b[j,s] + sum_k ne_b[j,k] * inf_W[j,k,s]
//  * g_tother = min over batch-independent deviation sources:
//      - 0 if any ns_b != 0 (states would leave zero immediately)
//      - first spike of gen membranes under const drive gen_b (layer L-1
//        gets 2 updates per step: main + extra decode)
//      - first spike of inf membranes under const drive g_iin (layer L-1 2x)
// ---------------------------------------------------------------------------
__global__ __launch_bounds__(512) void consts_k(
    const float* __restrict__ inf_W, const float* __restrict__ inf_b,
    const float* __restrict__ ne_b,  const float* __restrict__ ns_b,
    const float* __restrict__ gen_b, const float* __restrict__ gen_tau,
    const float* __restrict__ gen_thr,
    const float* __restrict__ inf_tau, const float* __restrict__ inf_thr)
{
    __shared__ float neb_sm[NL*ND];
    __shared__ int red[17];
    const int tid = threadIdx.x;

    for (int i = tid; i < NL*ND; i += 512) neb_sm[i] = ne_b[i];
    __syncthreads();

    // iin GEMV: thread -> (j, s)
    const int j = tid >> 8, s = tid & (NS-1);
    float acc = inf_b[j*NS + s];
    {
        const float* W = inf_W + j*(ND*NS) + s;
        const float* e = neb_sm + j*ND;
        #pragma unroll 8
        for (int k = 0; k < ND; k++) acc += e[k] * W[k*NS];
    }
    g_iin[j*NS + s] = acc;

    int dev = (ns_b[tid] != 0.f) ? 0 : NT;   // tid covers NL*NS = 512

    // gen const-drive scan: d = tid, both layers
    #pragma unroll
    for (int jj = 0; jj < NL; jj++) {
        const float gbv = gen_b[jj*ND + tid];
        const float dec = expf(-1.f / fmaxf(gen_tau[jj*ND + tid], 1.f));
        const float thr = gen_thr[jj*ND + tid];
        const int nup = (jj == NL-1) ? 2*NT : NT;
        float m = 0.f;
        int first = NT;
        for (int u = 0; u < nup; u++) {
            m = m*dec + gbv;
            if (m >= thr) { first = (jj == NL-1) ? (u >> 1) : u; break; }
        }
        dev = min(dev, first);
    }

    // inf const-drive scan: this thread's own (j, s), drive = acc
    {
        const float dec = expf(-1.f / fmaxf(inf_tau[j*NS + s], 1.f));
        const float thr = inf_thr[j*NS + s];
        const int nup = (j == NL-1) ? 2*NT : NT;
        float m = 0.f;
        int first = NT;
        for (int u = 0; u < nup; u++) {
            m = m*dec + acc;
            if (m >= thr) { first = (j == NL-1) ? (u >> 1) : u; break; }
        }
        dev = min(dev, first);
    }

    int tmin = blk_min(dev, red);
    if (tid == 0) g_tother = tmin;
}

// ---------------------------------------------------------------------------
// Encoder GEMM with fused embedding gather (unchanged, audited)
// ---------------------------------------------------------------------------
__global__ __launch_bounds__(256) void enc_gemm_k(
    const int* __restrict__ ids, const float* __restrict__ tok,
    const float* __restrict__ pos, const float* __restrict__ W,
    const float* __restrict__ bias)
{
    __shared__ float As[16][65];
    __shared__ float Bs[16][128];
    __shared__ int ids_sm[64];

    const int tid = threadIdx.x;
    const int m0 = blockIdx.y * 64;
    const int n0 = blockIdx.x * 128;
    if (tid < 64) ids_sm[tid] = ids[m0 + tid];
    __syncthreads();

    const int ty = tid >> 4, tx = tid & 15;
    const int arow = tid >> 2, kc = (tid & 3) * 4;
    const int gid  = ids_sm[arow];
    const int trow = (m0 + arow) & (NT - 1);

    float acc[4][8];
    #pragma unroll
    for (int i = 0; i < 4; i++)
        #pragma unroll
        for (int jj = 0; jj < 8; jj++) acc[i][jj] = 0.f;

    for (int k0 = 0; k0 < ND; k0 += 16) {
        float4 t4 = *(const float4*)&tok[gid*ND + k0 + kc];
        float4 p4 = *(const float4*)&pos[trow*ND + k0 + kc];
        As[kc+0][arow] = t4.x + p4.x;
        As[kc+1][arow] = t4.y + p4.y;
        As[kc+2][arow] = t4.z + p4.z;
        As[kc+3][arow] = t4.w + p4.w;
        #pragma unroll
        for (int i = 0; i < 2; i++) {
            int idx = tid*2 + i;
            int br = idx >> 5, bc = (idx & 31) * 4;
            *(float4*)&Bs[br][bc] = *(const float4*)&W[(k0+br)*ND + n0 + bc];
        }
        __syncthreads();
        #pragma unroll
        for (int kk = 0; kk < 16; kk++) {
            float a[4], bb[8];
            #pragma unroll
            for (int i = 0; i < 4; i++) a[i] = As[kk][ty*4+i];
            #pragma unroll
            for (int jj = 0; jj < 8; jj++) bb[jj] = Bs[kk][tx*8+jj];
            #pragma unroll
            for (int i = 0; i < 4; i++)
                #pragma unroll
                for (int jj = 0; jj < 8; jj++) acc[i][jj] += a[i]*bb[jj];
        }
        __syncthreads();
    }
    #pragma unroll
    for (int i = 0; i < 4; i++) {
        const int m = m0 + ty*4 + i;
        #pragma unroll
        for (int jj = 0; jj < 8; jj++) {
            const int n = n0 + tx*8 + jj;
            g_xenc[m*ND + n] = acc[i][jj] + bias[n];
        }
    }
}

// ---------------------------------------------------------------------------
// snap_k (grid NB, 512 threads):
//  pass 1: exact enc-LIF scan per (b,d) lane -> first enc spike time;
//          t_break(b) = min(block-min, g_tother)
//  pass 2: re-iterate the exact recurrences for t_break steps to snapshot
//          m_enc / m_gen / m_inf (bit-identical fp op sequence), and zero
//          g_preds rows t < t_break (final_pred == 0 before any deviation).
// ---------------------------------------------------------------------------
__global__ __launch_bounds__(512) void snap_k(
    const float* __restrict__ enc_tau, const float* __restrict__ enc_thr,
    const float* __restrict__ gen_b,  const float* __restrict__ gen_tau,
    const float* __restrict__ gen_thr,
    const float* __restrict__ inf_tau, const float* __restrict__ inf_thr)
{
    __shared__ int red[17];
    const int b = blockIdx.x;
    const int d = threadIdx.x;

    const float dec = expf(-1.f / fmaxf(enc_tau[d], 1.f));
    const float thr = enc_thr[d];
    const float* xp = g_xenc + (b*NT)*ND + d;

    // pass 1: first enc spike (loads are m-independent -> unroll gives MLP)
    float m = 0.f;
    int first = NT;
    #pragma unroll 8
    for (int t = 0; t < NT; t++) {
        m = m*dec + xp[t*ND];
        float s = (m >= thr) ? 1.f : 0.f;
        if (s != 0.f && first == NT) first = t;
        m *= (1.f - s);
    }
    int tb = blk_min(first, red);
    tb = min(tb, g_tother);
    if (d == 0) g_tbreak[b] = tb;

    // pass 2: membrane snapshots at entry of step tb
    m = 0.f;
    for (int t = 0; t < tb; t++) {
        m = m*dec + xp[t*ND];
        float s = (m >= thr) ? 1.f : 0.f;
        m *= (1.f - s);
    }
    g_menc[b*ND + d] = m;

    #pragma unroll
    for (int jj = 0; jj < NL; jj++) {
        const float gbv = gen_b[jj*ND + d];
        const float gd  = expf(-1.f / fmaxf(gen_tau[jj*ND + d], 1.f));
        const float gt  = gen_thr[jj*ND + d];
        const int nup = (jj == NL-1) ? 2*tb : tb;
        float mg = 0.f;
        for (int u = 0; u < nup; u++) {
            mg = mg*gd + gbv;
            float s = (mg >= gt) ? 1.f : 0.f;
            mg *= (1.f - s);
        }
        g_mgen[(b*NL + jj)*ND + d] = mg;
    }
    {
        const int j = d >> 8, s = d & (NS-1);   // 512 threads cover (j,s)
        const float drive = g_iin[j*NS + s];
        const float idc = expf(-1.f / fmaxf(inf_tau[j*NS + s], 1.f));
        const float it  = inf_thr[j*NS + s];
        const int nup = (j == NL-1) ? 2*tb : tb;
        float mi = 0.f;
        for (int u = 0; u < nup; u++) {
            mi = mi*idc + drive;
            float sp = (mi >= it) ? 1.f : 0.f;
            mi *= (1.f - sp);
        }
        g_minf[(b*NL + j)*NS + s] = mi;
    }

    // zero preds for t < tb
    float* pp = g_preds + (b*NT)*ND + d;
    for (int t = 0; t < tb; t++) pp[t*ND] = 0.f;
}

// ---------------------------------------------------------------------------
// Single-barrier block reduction for 128 threads (4 warps), parity-buffered.
// ---------------------------------------------------------------------------
struct Red3 { float s, q; int nz; };

__device__ __forceinline__ Red3 blk_reduce4(
    float s, float q, int nz, int p,
    float2 (*red2)[4], int (*rnz)[4], int w, int lane)
{
    #pragma unroll
    for (int o = 16; o > 0; o >>= 1) {
        s += __shfl_xor_sync(0xffffffffu, s, o);
        q += __shfl_xor_sync(0xffffffffu, q, o);
    }
    int wn = __any_sync(0xffffffffu, nz);
    if (lane == 0) { red2[p][w] = make_float2(s, q); rnz[p][w] = wn; }
    __syncthreads();
    Red3 r; r.s = 0.f; r.q = 0.f; r.nz = 0;
    #pragma unroll
    for (int i = 0; i < 4; i++) {
        float2 v = red2[p][i];
        r.s += v.x; r.q += v.y; r.nz |= rnz[p][i];
    }
    return r;
}

// ---------------------------------------------------------------------------
// Sequential fallback: steps [t_break, NT) from snapshots. General & exact.
// With no deviation (t_break == NT) it exits immediately.
// ---------------------------------------------------------------------------
__global__ __launch_bounds__(128) void recur_fb_k(
    const float* __restrict__ gen_W, const float* __restrict__ gen_b,
    const float* __restrict__ gen_tau, const float* __restrict__ gen_thr,
    const float* __restrict__ inf_W, const float* __restrict__ inf_b,
    const float* __restrict__ inf_tau, const float* __restrict__ inf_thr,
    const float* __restrict__ ne_g, const float* __restrict__ ne_b,
    const float* __restrict__ ns_g, const float* __restrict__ ns_b,
    const float* __restrict__ enc_tau, const float* __restrict__ enc_thr)
{
    const int b = blockIdx.x;
    const int t0 = g_tbreak[b];
    if (t0 >= NT) return;          // uniform early exit (fast path)

    __shared__ __align__(16) float st_sm[NL][NS];
    __shared__ __align__(16) float err_sm[ND];
    __shared__ float2 red2[2][4];
    __shared__ int    rnz[2][4];

    const int tid  = threadIdx.x;
    const int w    = tid >> 5, lane = tid & 31;
    const int d0   = tid * 4;
    const bool hasS = (tid < NS/4);
    const int s0   = tid * 4;

    float dec_e[4], thr_e[4], m_enc[4];
    #pragma unroll
    for (int c = 0; c < 4; c++) {
        dec_e[c] = expf(-1.f / fmaxf(enc_tau[d0+c], 1.f));
        thr_e[c] = enc_thr[d0+c];
        m_enc[c] = g_menc[b*ND + d0 + c];
    }
    float gb[NL][4], gdec[NL][4], gthr[NL][4], negv[NL][4], nebv[NL][4], m_gen[NL][4];
    #pragma unroll
    for (int j = 0; j < NL; j++)
        #pragma unroll
        for (int c = 0; c < 4; c++) {
            const int i = j*ND + d0 + c;
            gb[j][c]   = gen_b[i];
            gdec[j][c] = expf(-1.f / fmaxf(gen_tau[i], 1.f));
            gthr[j][c] = gen_thr[i];
            negv[j][c] = ne_g[i];
            nebv[j][c] = ne_b[i];
            m_gen[j][c] = g_mgen[(b*NL + j)*ND + d0 + c];
        }
    float ib[NL][4], idec[NL][4], ithr[NL][4], nsgv[NL][4], nsbv[NL][4], m_inf[NL][4];
    #pragma unroll
    for (int j = 0; j < NL; j++)
        #pragma unroll
        for (int c = 0; c < 4; c++) {
            ib[j][c] = 0.f; idec[j][c] = 0.f; ithr[j][c] = 0.f;
            nsgv[j][c] = 0.f; nsbv[j][c] = 0.f; m_inf[j][c] = 0.f;
        }
    if (hasS) {
        #pragma unroll
        for (int j = 0; j < NL; j++)
            #pragma unroll
            for (int c = 0; c < 4; c++) {
                const int i = j*NS + s0 + c;
                ib[j][c]   = inf_b[i];
                idec[j][c] = expf(-1.f / fmaxf(inf_tau[i], 1.f));
                ithr[j][c] = inf_thr[i];
                nsgv[j][c] = ns_g[i];
                nsbv[j][c] = ns_b[i];
                m_inf[j][c] = g_minf[(b*NL + j)*NS + s0 + c];
            }
        #pragma unroll
        for (int c = 0; c < 4; c++) { st_sm[0][s0+c] = 0.f; st_sm[1][s0+c] = 0.f; }
    }

    int neb_nz[NL], nsb_nz[NL];
    #pragma unroll
    for (int j = 0; j < NL; j++) {
        int a = 0, bn = 0;
        #pragma unroll
        for (int c = 0; c < 4; c++) a |= (nebv[j][c] != 0.f);
        if (hasS)
            #pragma unroll
            for (int c = 0; c < 4; c++) bn |= (nsbv[j][c] != 0.f);
        neb_nz[j] = __syncthreads_or(a);
        nsb_nz[j] = __syncthreads_or(bn);
    }

    float st_r[NL][4] = {{0,0,0,0},{0,0,0,0}};
    int   st_nz[NL] = {0, 0};
    __syncthreads();

    const float* xp = g_xenc  + (b*NT)*ND + d0;
    float*       pp = g_preds + (b*NT)*ND + d0;
    int p = 0;

    for (int t = t0; t < NT; t++) {
        float bu[4];
        {
            float4 x4 = *(const float4*)&xp[t*ND];
            float xi[4] = {x4.x, x4.y, x4.z, x4.w};
            #pragma unroll
            for (int c = 0; c < 4; c++) {
                float m = m_enc[c]*dec_e[c] + xi[c];
                float s = (m >= thr_e[c]) ? 1.f : 0.f;
                m_enc[c] = m*(1.f - s);
                bu[c] = s;
            }
        }
        #pragma unroll
        for (int j = 0; j < NL; j++) {
            float gin[4] = {gb[j][0], gb[j][1], gb[j][2], gb[j][3]};
            if (st_nz[j]) {
                const float* Wp = gen_W + j*(NS*ND) + d0;
                for (int k = 0; k < NS; k++) {
                    float sv = st_sm[j][k];
                    float4 w4 = *(const float4*)&Wp[k*ND];
                    gin[0] += sv*w4.x; gin[1] += sv*w4.y;
                    gin[2] += sv*w4.z; gin[3] += sv*w4.w;
                }
            }
            float v[4];
            #pragma unroll
            for (int c = 0; c < 4; c++) {
                float mg = m_gen[j][c]*gdec[j][c] + gin[c];
                float pr = (mg >= gthr[j][c]) ? 1.f : 0.f;
                m_gen[j][c] = mg*(1.f - pr);
                v[c] = bu[c] - pr;
            }
            float s = (v[0]+v[1])+(v[2]+v[3]);
            float q = (v[0]*v[0]+v[1]*v[1])+(v[2]*v[2]+v[3]*v[3]);
            int   a = (v[0]!=0.f)|(v[1]!=0.f)|(v[2]!=0.f)|(v[3]!=0.f);
            Red3 r = blk_reduce4(s, q, a, p, red2, rnz, w, lane); p ^= 1;
            float mu   = r.s * (1.f/ND);
            float rstd = rsqrtf(fmaxf(r.q*(1.f/ND) - mu*mu, 0.f) + 1e-5f);
            float e[4];
            #pragma unroll
            for (int c = 0; c < 4; c++) e[c] = (v[c]-mu)*rstd*negv[j][c] + nebv[j][c];
            *(float4*)&err_sm[d0] = make_float4(e[0], e[1], e[2], e[3]);
            const int enz = r.nz | neb_nz[j];
            if (enz) __syncthreads();
            #pragma unroll
            for (int c = 0; c < 4; c++) bu[c] = e[c];

            float nsv[4] = {0,0,0,0};
            if (hasS) {
                float iin[4] = {ib[j][0], ib[j][1], ib[j][2], ib[j][3]};
                if (enz) {
                    const float* Wp = inf_W + j*(ND*NS) + s0;
                    for (int k = 0; k < ND; k++) {
                        float ev = err_sm[k];
                        float4 w4 = *(const float4*)&Wp[k*NS];
                        iin[0] += ev*w4.x; iin[1] += ev*w4.y;
                        iin[2] += ev*w4.z; iin[3] += ev*w4.w;
                    }
                }
                #pragma unroll
                for (int c = 0; c < 4; c++) {
                    float mi = m_inf[j][c]*idec[j][c] + iin[c];
                    float su = (mi >= ithr[j][c]) ? 1.f : 0.f;
                    m_inf[j][c] = mi*(1.f - su);
                    nsv[c] = st_r[j][c] + su;
                }
            }
            float s2 = (nsv[0]+nsv[1])+(nsv[2]+nsv[3]);
            float q2 = (nsv[0]*nsv[0]+nsv[1]*nsv[1])+(nsv[2]*nsv[2]+nsv[3]*nsv[3]);
            int   a2 = (nsv[0]!=0.f)|(nsv[1]!=0.f)|(nsv[2]!=0.f)|(nsv[3]!=0.f);
            Red3 r2 = blk_reduce4(s2, q2, a2, p, red2, rnz, w, lane); p ^= 1;
            float mu2   = r2.s * (1.f/NS);
            float rstd2 = rsqrtf(fmaxf(r2.q*(1.f/NS) - mu2*mu2, 0.f) + 1e-5f);
            if (hasS) {
                float nst[4];
                #pragma unroll
                for (int c = 0; c < 4; c++) {
                    nst[c] = (nsv[c]-mu2)*rstd2*nsgv[j][c] + nsbv[j][c];
                    st_r[j][c] = nst[c];
                }
                *(float4*)&st_sm[j][s0] = make_float4(nst[0], nst[1], nst[2], nst[3]);
            }
            const int newnz = r2.nz | nsb_nz[j];
            if (newnz) __syncthreads();
            st_nz[j] = newnz;
        }
        {
            const int j = NL-1;
            float gin[4] = {gb[j][0], gb[j][1], gb[j][2], gb[j][3]};
            if (st_nz[j]) {
                const float* Wp = gen_W + j*(NS*ND) + d0;
                for (int k = 0; k < NS; k++) {
                    float sv = st_sm[j][k];
                    float4 w4 = *(const float4*)&Wp[k*ND];
                    gin[0] += sv*w4.x; gin[1] += sv*w4.y;
                    gin[2] += sv*w4.z; gin[3] += sv*w4.w;
                }
            }
            float fp[4], v[4];
            #pragma unroll
            for (int c = 0; c < 4; c++) {
                float mg = m_gen[j][c]*gdec[j][c] + gin[c];
                fp[c] = (mg >= gthr[j][c]) ? 1.f : 0.f;
                m_gen[j][c] = mg*(1.f - fp[c]);
                v[c] = -fp[c];
            }
            *(float4*)&pp[t*ND] = make_float4(fp[0], fp[1], fp[2], fp[3]);

            float s = (v[0]+v[1])+(v[2]+v[3]);
            float q = (v[0]*v[0]+v[1]*v[1])+(v[2]*v[2]+v[3]*v[3]);
            int   a = (v[0]!=0.f)|(v[1]!=0.f)|(v[2]!=0.f)|(v[3]!=0.f);
            Red3 r = blk_reduce4(s, q, a, p, red2, rnz, w, lane); p ^= 1;
            float mu   = r.s * (1.f/ND);
            float rstd = rsqrtf(fmaxf(r.q*(1.f/ND) - mu*mu, 0.f) + 1e-5f);
            float e2[4];
            #pragma unroll
            for (int c = 0; c < 4; c++) e2[c] = (v[c]-mu)*rstd*negv[j][c] + nebv[j][c];
            *(float4*)&err_sm[d0] = make_float4(e2[0], e2[1], e2[2], e2[3]);
            const int enz2 = r.nz | neb_nz[j];
            if (enz2) __syncthreads();
            if (hasS) {
                float iin[4] = {ib[j][0], ib[j][1], ib[j][2], ib[j][3]};
                if (enz2) {
                    const float* Wp = inf_W + j*(ND*NS) + s0;
                    for (int k = 0; k < ND; k++) {
                        float ev = err_sm[k];
                        float4 w4 = *(const float4*)&Wp[k*NS];
                        iin[0] += ev*w4.x; iin[1] += ev*w4.y;
                        iin[2] += ev*w4.z; iin[3] += ev*w4.w;
                    }
                }
                #pragma unroll
                for (int c = 0; c < 4; c++) {
                    float mi = m_inf[j][c]*idec[j][c] + iin[c];
                    float su = (mi >= ithr[j][c]) ? 1.f : 0.f;
                    m_inf[j][c] = mi*(1.f - su);
                }
            }
        }
    }
}

// ---------------------------------------------------------------------------
// Epilogue: h = gelu(LN(preds)); per-64-row nonzero flags.
// ---------------------------------------------------------------------------
__global__ __launch_bounds__(512) void epilogue_k(
    const float* __restrict__ og, const float* __restrict__ ob)
{
    __shared__ float2 red[17];
    const int m = blockIdx.x;
    const int d = threadIdx.x;
    float v = g_preds[m*ND + d];
    float2 s = blk_sum2(v, v*v, red);
    float mu = s.x * (1.f/ND);
    float rstd = rsqrtf(fmaxf(s.y*(1.f/ND) - mu*mu, 0.f) + 1e-5f);
    float x = (v - mu)*rstd*og[d] + ob[d];
    float hv = 0.5f * x * (1.f + erff(x * 0.70710678118654752440f));
    g_h[m*ND + d] = hv;
    int nz = __syncthreads_or(hv != 0.f);
    if (d == 0 && nz) atomicOr(&g_rowflag[m >> 6], 1);
}

// ---------------------------------------------------------------------------
// Output GEMM with exact all-zero fast path (bias broadcast).
// ---------------------------------------------------------------------------
__global__ __launch_bounds__(256) void out_gemm_k(
    const float* __restrict__ Wo, const float* __restrict__ bias,
    float* __restrict__ out)
{
    const int tid = threadIdx.x;
    const int m0 = blockIdx.y * 64;
    const int n0 = blockIdx.x * 128;

    if (g_rowflag[blockIdx.y] == 0) {
        const int c4 = (tid & 31) * 4;
        const int r0 = tid >> 5;
        const float4 bv = *(const float4*)&bias[n0 + c4];
        #pragma unroll
        for (int r = r0; r < 64; r += 8)
            *(float4*)&out[(m0 + r)*NV + n0 + c4] = bv;
        return;
    }

    __shared__ float As[16][65];
    __shared__ float Bs[16][128];
    const int ty = tid >> 4, tx = tid & 15;
    const int arow = tid >> 2, kc = (tid & 3) * 4;

    float acc[4][8];
    #pragma unroll
    for (int i = 0; i < 4; i++)
        #pragma unroll
        for (int jj = 0; jj < 8; jj++) acc[i][jj] = 0.f;

    for (int k0 = 0; k0 < ND; k0 += 16) {
        float4 a4 = *(const float4*)&g_h[(m0 + arow)*ND + k0 + kc];
        As[kc+0][arow] = a4.x;
        As[kc+1][arow] = a4.y;
        As[kc+2][arow] = a4.z;
        As[kc+3][arow] = a4.w;
        #pragma unroll
        for (int i = 0; i < 2; i++) {
            int idx = tid*2 + i;
            int br = idx >> 5, bc = (idx & 31) * 4;
            *(float4*)&Bs[br][bc] = *(const float4*)&Wo[(k0+br)*NV + n0 + bc];
        }
        __syncthreads();
        #pragma unroll
        for (int kk = 0; kk < 16; kk++) {
            float a[4], bb[8];
            #pragma unroll
            for (int i = 0; i < 4; i++) a[i] = As[kk][ty*4+i];
            #pragma unroll
            for (int jj = 0; jj < 8; jj++) bb[jj] = Bs[kk][tx*8+jj];
            #pragma unroll
            for (int i = 0; i < 4; i++)
                #pragma unroll
                for (int jj = 0; jj < 8; jj++) acc[i][jj] += a[i]*bb[jj];
        }
        __syncthreads();
    }
    #pragma unroll
    for (int i = 0; i < 4; i++) {
        const int m = m0 + ty*4 + i;
        #pragma unroll
        for (int jj = 0; jj < 8; jj++) {
            const int n = n0 + tx*8 + jj;
            out[m*NV + n] = acc[i][jj] + bias[n];
        }
    }
}

// ---------------------------------------------------------------------------
// Entry point
// ---------------------------------------------------------------------------
extern "C" void kernel_launch(void* const* d_in, const int* in_sizes, int n_in,
                              void* d_out, int out_size)
{
    (void)in_sizes; (void)n_in; (void)out_size;
    const int*   ids    = (const int*)  d_in[0];
    const float* tok    = (const float*)d_in[1];
    const float* pos    = (const float*)d_in[2];
    const float* encW   = (const float*)d_in[3];
    const float* encb   = (const float*)d_in[4];
    const float* enctau = (const float*)d_in[5];
    const float* encthr = (const float*)d_in[6];
    const float* genW   = (const float*)d_in[7];
    const float* genb   = (const float*)d_in[8];
    const float* gentau = (const float*)d_in[9];
    const float* genthr = (const float*)d_in[10];
    const float* infW   = (const float*)d_in[11];
    const float* infb   = (const float*)d_in[12];
    const float* inftau = (const float*)d_in[13];
    const float* infthr = (const float*)d_in[14];
    const float* neg    = (const float*)d_in[15];
    const float* neb    = (const float*)d_in[16];
    const float* nsg    = (const float*)d_in[17];
    const float* nsb    = (const float*)d_in[18];
    const float* outg   = (const float*)d_in[19];
    const float* outb   = (const float*)d_in[20];
    const float* outW   = (const float*)d_in[21];
    const float* outb2  = (const float*)d_in[22];
    float* out = (float*)d_out;

    init_k<<<1, 32>>>();
    consts_k<<<1, 512>>>(infW, infb, neb, nsb, genb, gentau, genthr,
                         inftau, infthr);
    enc_gemm_k<<<dim3(ND/128, NM/64), 256>>>(ids, tok, pos, encW, encb);
    snap_k<<<NB, 512>>>(enctau, encthr, genb, gentau, genthr, inftau, infthr);
    recur_fb_k<<<NB, 128>>>(genW, genb, gentau, genthr,
                            infW, infb, inftau, infthr,
                            neg, neb, nsg, nsb, enctau, encthr);
    epilogue_k<<<NM, ND>>>(outg, outb);
    out_gemm_k<<<dim3(NV/128, NM/64), 256>>>(outW, outb2, out);
}

// round 11
// speedup vs baseline: 2.2811x; 1.1190x over previous
#include <cuda_runtime.h>
#include <math.h>

// Problem constants (fixed shapes)
#define NB 8
#define NT 256
#define ND 512
#define NS 256
#define NV 32000
#define NL 2
#define NM (NB*NT)   // 2048 rows

// ---------------------------------------------------------------------------
// Scratch (static device globals — no allocation)
// ---------------------------------------------------------------------------
__device__ float g_xenc [NM*ND];    // x @ enc_W + enc_b, all t
__device__ float g_preds[NM*ND];    // final_pred per (b,t) — only rows t>=tbreak valid
__device__ float g_h    [NM*ND];    // gelu(LN(preds))
__device__ int   g_rowflag[NM/64];  // per-64-row block: any nonzero in h?
__device__ int   g_tother;          // batch-independent first-deviation time
__device__ int   g_tbreak[NB];      // per-batch first-deviation time (atomicMin)
__device__ float g_iin  [NL*NS];    // const inf drive: ne_b @ inf_W + inf_b
__device__ float g_menc [NB*ND];    // membrane snapshots at t_break
__device__ float g_mgen [NB*NL*ND];
__device__ float g_minf [NB*NL*NS];

// ---------------------------------------------------------------------------
// Reductions
// ---------------------------------------------------------------------------
__device__ __forceinline__ float2 blk_sum2(float v, float v2, float2* red)
{
    #pragma unroll
    for (int o = 16; o > 0; o >>= 1) {
        v  += __shfl_xor_sync(0xffffffffu, v,  o);
        v2 += __shfl_xor_sync(0xffffffffu, v2, o);
    }
    const int w = threadIdx.x >> 5;
    const int lane = threadIdx.x & 31;
    if (lane == 0) red[w] = make_float2(v, v2);
    __syncthreads();
    if (w == 0) {
        float a = (lane < 16) ? red[lane].x : 0.f;
        float b = (lane < 16) ? red[lane].y : 0.f;
        #pragma unroll
        for (int o = 8; o > 0; o >>= 1) {
            a += __shfl_xor_sync(0xffffffffu, a, o);
            b += __shfl_xor_sync(0xffffffffu, b, o);
        }
        if (lane == 0) red[16] = make_float2(a, b);
    }
    __syncthreads();
    return red[16];
}

// block-wide min over up to 512 threads
__device__ __forceinline__ int blk_min(int v, int* red)
{
    #pragma unroll
    for (int o = 16; o > 0; o >>= 1)
        v = min(v, __shfl_xor_sync(0xffffffffu, v, o));
    const int w = threadIdx.x >> 5;
    const int lane = threadIdx.x & 31;
    const int nw = (blockDim.x + 31) >> 5;
    if (lane == 0) red[w] = v;
    __syncthreads();
    if (w == 0) {
        int a = (lane < nw) ? red[lane] : 0x7fffffff;
        #pragma unroll
        for (int o = 8; o > 0; o >>= 1)
            a = min(a, __shfl_xor_sync(0xffffffffu, a, o));
        if (lane == 0) red[16] = a;
    }
    __syncthreads();
    return red[16];
}

// ---------------------------------------------------------------------------
// Init: zero row flags
// ---------------------------------------------------------------------------
__global__ void init_k()
{
    if (threadIdx.x < NM/64) g_rowflag[threadIdx.x] = 0;
}

// ---------------------------------------------------------------------------
// consts_k (1 CTA, 512 threads):
//  * g_iin[j,s] = inf_b[j,s] + sum_k ne_b[j,k] * inf_W[j,k,s]
//  * g_tother = min over batch-independent deviation sources
//  * seeds g_tbreak[b] = g_tother (scan_k refines via atomicMin)
// ---------------------------------------------------------------------------
__global__ __launch_bounds__(512) void consts_k(
    const float* __restrict__ inf_W, const float* __restrict__ inf_b,
    const float* __restrict__ ne_b,  const float* __restrict__ ns_b,
    const float* __restrict__ gen_b, const float* __restrict__ gen_tau,
    const float* __restrict__ gen_thr,
    const float* __restrict__ inf_tau, const float* __restrict__ inf_thr)
{
    __shared__ float neb_sm[NL*ND];
    __shared__ int red[17];
    const int tid = threadIdx.x;

    for (int i = tid; i < NL*ND; i += 512) neb_sm[i] = ne_b[i];
    __syncthreads();

    // iin GEMV: thread -> (j, s)
    const int j = tid >> 8, s = tid & (NS-1);
    float acc = inf_b[j*NS + s];
    {
        const float* W = inf_W + j*(ND*NS) + s;
        const float* e = neb_sm + j*ND;
        #pragma unroll 8
        for (int k = 0; k < ND; k++) acc += e[k] * W[k*NS];
    }
    g_iin[j*NS + s] = acc;

    int dev = (ns_b[tid] != 0.f) ? 0 : NT;   // tid covers NL*NS = 512

    // gen const-drive scan: d = tid, both layers
    #pragma unroll
    for (int jj = 0; jj < NL; jj++) {
        const float gbv = gen_b[jj*ND + tid];
        const float dec = expf(-1.f / fmaxf(gen_tau[jj*ND + tid], 1.f));
        const float thr = gen_thr[jj*ND + tid];
        const int nup = (jj == NL-1) ? 2*NT : NT;
        float m = 0.f;
        int first = NT;
        for (int u = 0; u < nup; u++) {
            m = m*dec + gbv;
            if (m >= thr) { first = (jj == NL-1) ? (u >> 1) : u; break; }
        }
        dev = min(dev, first);
    }

    // inf const-drive scan: this thread's own (j, s), drive = acc
    {
        const float dec = expf(-1.f / fmaxf(inf_tau[j*NS + s], 1.f));
        const float thr = inf_thr[j*NS + s];
        const int nup = (j == NL-1) ? 2*NT : NT;
        float m = 0.f;
        int first = NT;
        for (int u = 0; u < nup; u++) {
            m = m*dec + acc;
            if (m >= thr) { first = (j == NL-1) ? (u >> 1) : u; break; }
        }
        dev = min(dev, first);
    }

    int tmin = blk_min(dev, red);
    if (tid == 0) g_tother = tmin;
    if (tid < NB) g_tbreak[tid] = tmin;     // seed; scan_k refines
}

// ---------------------------------------------------------------------------
// Encoder GEMM with fused embedding gather (audited, unchanged)
// ---------------------------------------------------------------------------
__global__ __launch_bounds__(256) void enc_gemm_k(
    const int* __restrict__ ids, const float* __restrict__ tok,
    const float* __restrict__ pos, const float* __restrict__ W,
    const float* __restrict__ bias)
{
    __shared__ float As[16][65];
    __shared__ float Bs[16][128];
    __shared__ int ids_sm[64];

    const int tid = threadIdx.x;
    const int m0 = blockIdx.y * 64;
    const int n0 = blockIdx.x * 128;
    if (tid < 64) ids_sm[tid] = ids[m0 + tid];
    __syncthreads();

    const int ty = tid >> 4, tx = tid & 15;
    const int arow = tid >> 2, kc = (tid & 3) * 4;
    const int gid  = ids_sm[arow];
    const int trow = (m0 + arow) & (NT - 1);

    float acc[4][8];
    #pragma unroll
    for (int i = 0; i < 4; i++)
        #pragma unroll
        for (int jj = 0; jj < 8; jj++) acc[i][jj] = 0.f;

    for (int k0 = 0; k0 < ND; k0 += 16) {
        float4 t4 = *(const float4*)&tok[gid*ND + k0 + kc];
        float4 p4 = *(const float4*)&pos[trow*ND + k0 + kc];
        As[kc+0][arow] = t4.x + p4.x;
        As[kc+1][arow] = t4.y + p4.y;
        As[kc+2][arow] = t4.z + p4.z;
        As[kc+3][arow] = t4.w + p4.w;
        #pragma unroll
        for (int i = 0; i < 2; i++) {
            int idx = tid*2 + i;
            int br = idx >> 5, bc = (idx & 31) * 4;
            *(float4*)&Bs[br][bc] = *(const float4*)&W[(k0+br)*ND + n0 + bc];
        }
        __syncthreads();
        #pragma unroll
        for (int kk = 0; kk < 16; kk++) {
            float a[4], bb[8];
            #pragma unroll
            for (int i = 0; i < 4; i++) a[i] = As[kk][ty*4+i];
            #pragma unroll
            for (int jj = 0; jj < 8; jj++) bb[jj] = Bs[kk][tx*8+jj];
            #pragma unroll
            for (int i = 0; i < 4; i++)
                #pragma unroll
                for (int jj = 0; jj < 8; jj++) acc[i][jj] += a[i]*bb[jj];
        }
        __syncthreads();
    }
    #pragma unroll
    for (int i = 0; i < 4; i++) {
        const int m = m0 + ty*4 + i;
        #pragma unroll
        for (int jj = 0; jj < 8; jj++) {
            const int n = n0 + tx*8 + jj;
            g_xenc[m*ND + n] = acc[i][jj] + bias[n];
        }
    }
}

// ---------------------------------------------------------------------------
// scan_k (grid (4, NB), 128 threads): exact enc-LIF scan per (b,d) lane;
// per-CTA min of first spike time -> atomicMin into g_tbreak[b].
// ---------------------------------------------------------------------------
__global__ __launch_bounds__(128) void scan_k(
    const float* __restrict__ enc_tau, const float* __restrict__ enc_thr)
{
    __shared__ int red[17];
    const int b = blockIdx.y;
    const int d = blockIdx.x * 128 + threadIdx.x;

    const float dec = expf(-1.f / fmaxf(enc_tau[d], 1.f));
    const float thr = enc_thr[d];
    const float* xp = g_xenc + (b*NT)*ND + d;

    float m = 0.f;
    int first = NT;
    #pragma unroll 8
    for (int t = 0; t < NT; t++) {
        m = m*dec + xp[t*ND];
        float s = (m >= thr) ? 1.f : 0.f;
        if (s != 0.f && first == NT) first = t;
        m *= (1.f - s);
    }
    int tb = blk_min(first, red);
    if (threadIdx.x == 0 && tb < NT) atomicMin(&g_tbreak[b], tb);
}

// ---------------------------------------------------------------------------
// snap2_k (grid NB, 512 threads): membrane snapshots at t_break.
// Early-exits when t_break == NT (fast path: snapshots unused).
// Bit-identical fp op sequence to the reference recurrences.
// ---------------------------------------------------------------------------
__global__ __launch_bounds__(512) void snap2_k(
    const float* __restrict__ enc_tau, const float* __restrict__ enc_thr,
    const float* __restrict__ gen_b,  const float* __restrict__ gen_tau,
    const float* __restrict__ gen_thr,
    const float* __restrict__ inf_tau, const float* __restrict__ inf_thr)
{
    const int b = blockIdx.x;
    const int tb = g_tbreak[b];
    if (tb >= NT) return;                 // uniform: nothing downstream needs this

    const int d = threadIdx.x;
    const float dec = expf(-1.f / fmaxf(enc_tau[d], 1.f));
    const float thr = enc_thr[d];
    const float* xp = g_xenc + (b*NT)*ND + d;

    float m = 0.f;
    for (int t = 0; t < tb; t++) {
        m = m*dec + xp[t*ND];
        float s = (m >= thr) ? 1.f : 0.f;
        m *= (1.f - s);
    }
    g_menc[b*ND + d] = m;

    #pragma unroll
    for (int jj = 0; jj < NL; jj++) {
        const float gbv = gen_b[jj*ND + d];
        const float gd  = expf(-1.f / fmaxf(gen_tau[jj*ND + d], 1.f));
        const float gt  = gen_thr[jj*ND + d];
        const int nup = (jj == NL-1) ? 2*tb : tb;
        float mg = 0.f;
        for (int u = 0; u < nup; u++) {
            mg = mg*gd + gbv;
            float s = (mg >= gt) ? 1.f : 0.f;
            mg *= (1.f - s);
        }
        g_mgen[(b*NL + jj)*ND + d] = mg;
    }
    {
        const int j = d >> 8, s = d & (NS-1);
        const float drive = g_iin[j*NS + s];
        const float idc = expf(-1.f / fmaxf(inf_tau[j*NS + s], 1.f));
        const float it  = inf_thr[j*NS + s];
        const int nup = (j == NL-1) ? 2*tb : tb;
        float mi = 0.f;
        for (int u = 0; u < nup; u++) {
            mi = mi*idc + drive;
            float sp = (mi >= it) ? 1.f : 0.f;
            mi *= (1.f - sp);
        }
        g_minf[(b*NL + j)*NS + s] = mi;
    }
}

// ---------------------------------------------------------------------------
// Single-barrier block reduction for 128 threads (4 warps), parity-buffered.
// ---------------------------------------------------------------------------
struct Red3 { float s, q; int nz; };

__device__ __forceinline__ Red3 blk_reduce4(
    float s, float q, int nz, int p,
    float2 (*red2)[4], int (*rnz)[4], int w, int lane)
{
    #pragma unroll
    for (int o = 16; o > 0; o >>= 1) {
        s += __shfl_xor_sync(0xffffffffu, s, o);
        q += __shfl_xor_sync(0xffffffffu, q, o);
    }
    int wn = __any_sync(0xffffffffu, nz);
    if (lane == 0) { red2[p][w] = make_float2(s, q); rnz[p][w] = wn; }
    __syncthreads();
    Red3 r; r.s = 0.f; r.q = 0.f; r.nz = 0;
    #pragma unroll
    for (int i = 0; i < 4; i++) {
        float2 v = red2[p][i];
        r.s += v.x; r.q += v.y; r.nz |= rnz[p][i];
    }
    return r;
}

// ---------------------------------------------------------------------------
// Sequential fallback: steps [t_break, NT) from snapshots. General & exact.
// With no deviation (t_break == NT) it exits immediately.
// ---------------------------------------------------------------------------
__global__ __launch_bounds__(128) void recur_fb_k(
    const float* __restrict__ gen_W, const float* __restrict__ gen_b,
    const float* __restrict__ gen_tau, const float* __restrict__ gen_thr,
    const float* __restrict__ inf_W, const float* __restrict__ inf_b,
    const float* __restrict__ inf_tau, const float* __restrict__ inf_thr,
    const float* __restrict__ ne_g, const float* __restrict__ ne_b,
    const float* __restrict__ ns_g, const float* __restrict__ ns_b,
    const float* __restrict__ enc_tau, const float* __restrict__ enc_thr)
{
    const int b = blockIdx.x;
    const int t0 = g_tbreak[b];
    if (t0 >= NT) return;          // uniform early exit (fast path)

    __shared__ __align__(16) float st_sm[NL][NS];
    __shared__ __align__(16) float err_sm[ND];
    __shared__ float2 red2[2][4];
    __shared__ int    rnz[2][4];

    const int tid  = threadIdx.x;
    const int w    = tid >> 5, lane = tid & 31;
    const int d0   = tid * 4;
    const bool hasS = (tid < NS/4);
    const int s0   = tid * 4;

    float dec_e[4], thr_e[4], m_enc[4];
    #pragma unroll
    for (int c = 0; c < 4; c++) {
        dec_e[c] = expf(-1.f / fmaxf(enc_tau[d0+c], 1.f));
        thr_e[c] = enc_thr[d0+c];
        m_enc[c] = g_menc[b*ND + d0 + c];
    }
    float gb[NL][4], gdec[NL][4], gthr[NL][4], negv[NL][4], nebv[NL][4], m_gen[NL][4];
    #pragma unroll
    for (int j = 0; j < NL; j++)
        #pragma unroll
        for (int c = 0; c < 4; c++) {
            const int i = j*ND + d0 + c;
            gb[j][c]   = gen_b[i];
            gdec[j][c] = expf(-1.f / fmaxf(gen_tau[i], 1.f));
            gthr[j][c] = gen_thr[i];
            negv[j][c] = ne_g[i];
            nebv[j][c] = ne_b[i];
            m_gen[j][c] = g_mgen[(b*NL + j)*ND + d0 + c];
        }
    float ib[NL][4], idec[NL][4], ithr[NL][4], nsgv[NL][4], nsbv[NL][4], m_inf[NL][4];
    #pragma unroll
    for (int j = 0; j < NL; j++)
        #pragma unroll
        for (int c = 0; c < 4; c++) {
            ib[j][c] = 0.f; idec[j][c] = 0.f; ithr[j][c] = 0.f;
            nsgv[j][c] = 0.f; nsbv[j][c] = 0.f; m_inf[j][c] = 0.f;
        }
    if (hasS) {
        #pragma unroll
        for (int j = 0; j < NL; j++)
            #pragma unroll
            for (int c = 0; c < 4; c++) {
                const int i = j*NS + s0 + c;
                ib[j][c]   = inf_b[i];
                idec[j][c] = expf(-1.f / fmaxf(inf_tau[i], 1.f));
                ithr[j][c] = inf_thr[i];
                nsgv[j][c] = ns_g[i];
                nsbv[j][c] = ns_b[i];
                m_inf[j][c] = g_minf[(b*NL + j)*NS + s0 + c];
            }
        #pragma unroll
        for (int c = 0; c < 4; c++) { st_sm[0][s0+c] = 0.f; st_sm[1][s0+c] = 0.f; }
    }

    int neb_nz[NL], nsb_nz[NL];
    #pragma unroll
    for (int j = 0; j < NL; j++) {
        int a = 0, bn = 0;
        #pragma unroll
        for (int c = 0; c < 4; c++) a |= (nebv[j][c] != 0.f);
        if (hasS)
            #pragma unroll
            for (int c = 0; c < 4; c++) bn |= (nsbv[j][c] != 0.f);
        neb_nz[j] = __syncthreads_or(a);
        nsb_nz[j] = __syncthreads_or(bn);
    }

    float st_r[NL][4] = {{0,0,0,0},{0,0,0,0}};
    int   st_nz[NL] = {0, 0};
    __syncthreads();

    const float* xp = g_xenc  + (b*NT)*ND + d0;
    float*       pp = g_preds + (b*NT)*ND + d0;
    int p = 0;

    for (int t = t0; t < NT; t++) {
        float bu[4];
        {
            float4 x4 = *(const float4*)&xp[t*ND];
            float xi[4] = {x4.x, x4.y, x4.z, x4.w};
            #pragma unroll
            for (int c = 0; c < 4; c++) {
                float m = m_enc[c]*dec_e[c] + xi[c];
                float s = (m >= thr_e[c]) ? 1.f : 0.f;
                m_enc[c] = m*(1.f - s);
                bu[c] = s;
            }
        }
        #pragma unroll
        for (int j = 0; j < NL; j++) {
            float gin[4] = {gb[j][0], gb[j][1], gb[j][2], gb[j][3]};
            if (st_nz[j]) {
                const float* Wp = gen_W + j*(NS*ND) + d0;
                for (int k = 0; k < NS; k++) {
                    float sv = st_sm[j][k];
                    float4 w4 = *(const float4*)&Wp[k*ND];
                    gin[0] += sv*w4.x; gin[1] += sv*w4.y;
                    gin[2] += sv*w4.z; gin[3] += sv*w4.w;
                }
            }
            float v[4];
            #pragma unroll
            for (int c = 0; c < 4; c++) {
                float mg = m_gen[j][c]*gdec[j][c] + gin[c];
                float pr = (mg >= gthr[j][c]) ? 1.f : 0.f;
                m_gen[j][c] = mg*(1.f - pr);
                v[c] = bu[c] - pr;
            }
            float s = (v[0]+v[1])+(v[2]+v[3]);
            float q = (v[0]*v[0]+v[1]*v[1])+(v[2]*v[2]+v[3]*v[3]);
            int   a = (v[0]!=0.f)|(v[1]!=0.f)|(v[2]!=0.f)|(v[3]!=0.f);
            Red3 r = blk_reduce4(s, q, a, p, red2, rnz, w, lane); p ^= 1;
            float mu   = r.s * (1.f/ND);
            float rstd = rsqrtf(fmaxf(r.q*(1.f/ND) - mu*mu, 0.f) + 1e-5f);
            float e[4];
            #pragma unroll
            for (int c = 0; c < 4; c++) e[c] = (v[c]-mu)*rstd*negv[j][c] + nebv[j][c];
            *(float4*)&err_sm[d0] = make_float4(e[0], e[1], e[2], e[3]);
            const int enz = r.nz | neb_nz[j];
            if (enz) __syncthreads();
            #pragma unroll
            for (int c = 0; c < 4; c++) bu[c] = e[c];

            float nsv[4] = {0,0,0,0};
            if (hasS) {
                float iin[4] = {ib[j][0], ib[j][1], ib[j][2], ib[j][3]};
                if (enz) {
                    const float* Wp = inf_W + j*(ND*NS) + s0;
                    for (int k = 0; k < ND; k++) {
                        float ev = err_sm[k];
                        float4 w4 = *(const float4*)&Wp[k*NS];
                        iin[0] += ev*w4.x; iin[1] += ev*w4.y;
                        iin[2] += ev*w4.z; iin[3] += ev*w4.w;
                    }
                }
                #pragma unroll
                for (int c = 0; c < 4; c++) {
                    float mi = m_inf[j][c]*idec[j][c] + iin[c];
                    float su = (mi >= ithr[j][c]) ? 1.f : 0.f;
                    m_inf[j][c] = mi*(1.f - su);
                    nsv[c] = st_r[j][c] + su;
                }
            }
            float s2 = (nsv[0]+nsv[1])+(nsv[2]+nsv[3]);
            float q2 = (nsv[0]*nsv[0]+nsv[1]*nsv[1])+(nsv[2]*nsv[2]+nsv[3]*nsv[3]);
            int   a2 = (nsv[0]!=0.f)|(nsv[1]!=0.f)|(nsv[2]!=0.f)|(nsv[3]!=0.f);
            Red3 r2 = blk_reduce4(s2, q2, a2, p, red2, rnz, w, lane); p ^= 1;
            float mu2   = r2.s * (1.f/NS);
            float rstd2 = rsqrtf(fmaxf(r2.q*(1.f/NS) - mu2*mu2, 0.f) + 1e-5f);
            if (hasS) {
                float nst[4];
                #pragma unroll
                for (int c = 0; c < 4; c++) {
                    nst[c] = (nsv[c]-mu2)*rstd2*nsgv[j][c] + nsbv[j][c];
                    st_r[j][c] = nst[c];
                }
                *(float4*)&st_sm[j][s0] = make_float4(nst[0], nst[1], nst[2], nst[3]);
            }
            const int newnz = r2.nz | nsb_nz[j];
            if (newnz) __syncthreads();
            st_nz[j] = newnz;
        }
        {
            const int j = NL-1;
            float gin[4] = {gb[j][0], gb[j][1], gb[j][2], gb[j][3]};
            if (st_nz[j]) {
                const float* Wp = gen_W + j*(NS*ND) + d0;
                for (int k = 0; k < NS; k++) {
                    float sv = st_sm[j][k];
                    float4 w4 = *(const float4*)&Wp[k*ND];
                    gin[0] += sv*w4.x; gin[1] += sv*w4.y;
                    gin[2] += sv*w4.z; gin[3] += sv*w4.w;
                }
            }
            float fp[4], v[4];
            #pragma unroll
            for (int c = 0; c < 4; c++) {
                float mg = m_gen[j][c]*gdec[j][c] + gin[c];
                fp[c] = (mg >= gthr[j][c]) ? 1.f : 0.f;
                m_gen[j][c] = mg*(1.f - fp[c]);
                v[c] = -fp[c];
            }
            *(float4*)&pp[t*ND] = make_float4(fp[0], fp[1], fp[2], fp[3]);

            float s = (v[0]+v[1])+(v[2]+v[3]);
            float q = (v[0]*v[0]+v[1]*v[1])+(v[2]*v[2]+v[3]*v[3]);
            int   a = (v[0]!=0.f)|(v[1]!=0.f)|(v[2]!=0.f)|(v[3]!=0.f);
            Red3 r = blk_reduce4(s, q, a, p, red2, rnz, w, lane); p ^= 1;
            float mu   = r.s * (1.f/ND);
            float rstd = rsqrtf(fmaxf(r.q*(1.f/ND) - mu*mu, 0.f) + 1e-5f);
            float e2[4];
            #pragma unroll
            for (int c = 0; c < 4; c++) e2[c] = (v[c]-mu)*rstd*negv[j][c] + nebv[j][c];
            *(float4*)&err_sm[d0] = make_float4(e2[0], e2[1], e2[2], e2[3]);
            const int enz2 = r.nz | neb_nz[j];
            if (enz2) __syncthreads();
            if (hasS) {
                float iin[4] = {ib[j][0], ib[j][1], ib[j][2], ib[j][3]};
                if (enz2) {
                    const float* Wp = inf_W + j*(ND*NS) + s0;
                    for (int k = 0; k < ND; k++) {
                        float ev = err_sm[k];
                        float4 w4 = *(const float4*)&Wp[k*NS];
                        iin[0] += ev*w4.x; iin[1] += ev*w4.y;
                        iin[2] += ev*w4.z; iin[3] += ev*w4.w;
                    }
                }
                #pragma unroll
                for (int c = 0; c < 4; c++) {
                    float mi = m_inf[j][c]*idec[j][c] + iin[c];
                    float su = (mi >= ithr[j][c]) ? 1.f : 0.f;
                    m_inf[j][c] = mi*(1.f - su);
                }
            }
        }
    }
}

// ---------------------------------------------------------------------------
// Epilogue: h = gelu(LN(preds)); rows with t < t_break use exact 0 (no load).
// ---------------------------------------------------------------------------
__global__ __launch_bounds__(512) void epilogue_k(
    const float* __restrict__ og, const float* __restrict__ ob)
{
    __shared__ float2 red[17];
    const int m = blockIdx.x;
    const int d = threadIdx.x;
    const int b = m >> 8, t = m & (NT-1);
    const int tb = g_tbreak[b];
    float v = (t < tb) ? 0.f : g_preds[m*ND + d];
    float2 s = blk_sum2(v, v*v, red);
    float mu = s.x * (1.f/ND);
    float rstd = rsqrtf(fmaxf(s.y*(1.f/ND) - mu*mu, 0.f) + 1e-5f);
    float x = (v - mu)*rstd*og[d] + ob[d];
    float hv = 0.5f * x * (1.f + erff(x * 0.70710678118654752440f));
    g_h[m*ND + d] = hv;
    int nz = __syncthreads_or(hv != 0.f);
    if (d == 0 && nz) atomicOr(&g_rowflag[m >> 6], 1);
}

// ---------------------------------------------------------------------------
// Output GEMM with exact all-zero fast path (bias broadcast).
// ---------------------------------------------------------------------------
__global__ __launch_bounds__(256) void out_gemm_k(
    const float* __restrict__ Wo, const float* __restrict__ bias,
    float* __restrict__ out)
{
    const int tid = threadIdx.x;
    const int m0 = blockIdx.y * 64;
    const int n0 = blockIdx.x * 128;

    if (g_rowflag[blockIdx.y] == 0) {
        const int c4 = (tid & 31) * 4;
        const int r0 = tid >> 5;
        const float4 bv = *(const float4*)&bias[n0 + c4];
        #pragma unroll
        for (int r = r0; r < 64; r += 8)
            *(float4*)&out[(m0 + r)*NV + n0 + c4] = bv;
        return;
    }

    __shared__ float As[16][65];
    __shared__ float Bs[16][128];
    const int ty = tid >> 4, tx = tid & 15;
    const int arow = tid >> 2, kc = (tid & 3) * 4;

    float acc[4][8];
    #pragma unroll
    for (int i = 0; i < 4; i++)
        #pragma unroll
        for (int jj = 0; jj < 8; jj++) acc[i][jj] = 0.f;

    for (int k0 = 0; k0 < ND; k0 += 16) {
        float4 a4 = *(const float4*)&g_h[(m0 + arow)*ND + k0 + kc];
        As[kc+0][arow] = a4.x;
        As[kc+1][arow] = a4.y;
        As[kc+2][arow] = a4.z;
        As[kc+3][arow] = a4.w;
        #pragma unroll
        for (int i = 0; i < 2; i++) {
            int idx = tid*2 + i;
            int br = idx >> 5, bc = (idx & 31) * 4;
            *(float4*)&Bs[br][bc] = *(const float4*)&Wo[(k0+br)*NV + n0 + bc];
        }
        __syncthreads();
        #pragma unroll
        for (int kk = 0; kk < 16; kk++) {
            float a[4], bb[8];
            #pragma unroll
            for (int i = 0; i < 4; i++) a[i] = As[kk][ty*4+i];
            #pragma unroll
            for (int jj = 0; jj < 8; jj++) bb[jj] = Bs[kk][tx*8+jj];
            #pragma unroll
            for (int i = 0; i < 4; i++)
                #pragma unroll
                for (int jj = 0; jj < 8; jj++) acc[i][jj] += a[i]*bb[jj];
        }
        __syncthreads();
    }
    #pragma unroll
    for (int i = 0; i < 4; i++) {
        const int m = m0 + ty*4 + i;
        #pragma unroll
        for (int jj = 0; jj < 8; jj++) {
            const int n = n0 + tx*8 + jj;
            out[m*NV + n] = acc[i][jj] + bias[n];
        }
    }
}

// ---------------------------------------------------------------------------
// Entry point
// ---------------------------------------------------------------------------
extern "C" void kernel_launch(void* const* d_in, const int* in_sizes, int n_in,
                              void* d_out, int out_size)
{
    (void)in_sizes; (void)n_in; (void)out_size;
    const int*   ids    = (const int*)  d_in[0];
    const float* tok    = (const float*)d_in[1];
    const float* pos    = (const float*)d_in[2];
    const float* encW   = (const float*)d_in[3];
    const float* encb   = (const float*)d_in[4];
    const float* enctau = (const float*)d_in[5];
    const float* encthr = (const float*)d_in[6];
    const float* genW   = (const float*)d_in[7];
    const float* genb   = (const float*)d_in[8];
    const float* gentau = (const float*)d_in[9];
    const float* genthr = (const float*)d_in[10];
    const float* infW   = (const float*)d_in[11];
    const float* infb   = (const float*)d_in[12];
    const float* inftau = (const float*)d_in[13];
    const float* infthr = (const float*)d_in[14];
    const float* neg    = (const float*)d_in[15];
    const float* neb    = (const float*)d_in[16];
    const float* nsg    = (const float*)d_in[17];
    const float* nsb    = (const float*)d_in[18];
    const float* outg   = (const float*)d_in[19];
    const float* outb   = (const float*)d_in[20];
    const float* outW   = (const float*)d_in[21];
    const float* outb2  = (const float*)d_in[22];
    float* out = (float*)d_out;

    init_k<<<1, 32>>>();
    consts_k<<<1, 512>>>(infW, infb, neb, nsb, genb, gentau, genthr,
                         inftau, infthr);
    enc_gemm_k<<<dim3(ND/128, NM/64), 256>>>(ids, tok, pos, encW, encb);
    scan_k<<<dim3(4, NB), 128>>>(enctau, encthr);
    snap2_k<<<NB, 512>>>(enctau, encthr, genb, gentau, genthr, inftau, infthr);
    recur_fb_k<<<NB, 128>>>(genW, genb, gentau, genthr,
                            infW, infb, inftau, infthr,
                            neg, neb, nsg, nsb, enctau, encthr);
    epilogue_k<<<NM, ND>>>(outg, outb);
    out_gemm_k<<<dim3(NV/128, NM/64), 256>>>(outW, outb2, out);
}